// round 12
// baseline (speedup 1.0000x reference)
#include <cuda_runtime.h>
#include <cuda_bf16.h>
#include <math.h>

#define BATCH 64
#define CH    64
#define NPT   256

typedef unsigned long long u64;

// ---------------- global scratch ----------------
__device__ float g_proj[BATCH * 160 * NPT];
__device__ float g_f[BATCH * CH * NPT];            // [b][ch][n]
__device__ float g_h[BATCH * 256 * NPT];           // [b][o][n] fp32
__device__ __nv_bfloat16 g_hh[BATCH * NPT * 256];  // [b][n][o] hi
__device__ __nv_bfloat16 g_hl[BATCH * NPT * 256];  // [b][n][o] lo
__device__ __nv_bfloat16 g_w2h[64 * 256];
__device__ __nv_bfloat16 g_w2l[64 * 256];

// ---------------- f32x2 helpers ----------------
__device__ __forceinline__ u64 f2pack(float a, float b) {
    u64 r;
    asm("mov.b64 %0, {%1, %2};" : "=l"(r) : "r"(__float_as_uint(a)), "r"(__float_as_uint(b)));
    return r;
}
__device__ __forceinline__ u64 ffma2(u64 a, u64 b, u64 c) {
    u64 d;
    asm("fma.rn.f32x2 %0, %1, %2, %3;" : "=l"(d) : "l"(a), "l"(b), "l"(c));
    return d;
}
__device__ __forceinline__ u64 fadd2(u64 a, u64 b) {
    u64 d;
    asm("add.rn.f32x2 %0, %1, %2;" : "=l"(d) : "l"(a), "l"(b));
    return d;
}
__device__ __forceinline__ void unpack2(u64 v, float& lo, float& hi) {
    unsigned int l, h;
    asm("mov.b64 {%0, %1}, %2;" : "=r"(l), "=r"(h) : "l"(v));
    lo = __uint_as_float(l);
    hi = __uint_as_float(h);
}
__device__ __forceinline__ float hsum2(u64 v) {
    float lo, hi;
    unpack2(v, lo, hi);
    return lo + hi;
}
__device__ __forceinline__ void bn_coef(const float* __restrict__ p, int ch, int cn,
                                        float& sc, float& sh) {
    float ga = __ldg(p + ch);
    float be = __ldg(p + cn + ch);
    float mu = __ldg(p + 2 * cn + ch);
    float va = __ldg(p + 3 * cn + ch);
    sc = ga * rsqrtf(va + 1e-5f);
    sh = fmaf(-mu, sc, be);
}

// mma.sync m16n8k16 bf16: d += a @ b
__device__ __forceinline__ void mma_bf16(float* d, const unsigned int* a, const unsigned int* b) {
    asm volatile("mma.sync.aligned.m16n8k16.row.col.f32.bf16.bf16.f32 "
        "{%0,%1,%2,%3}, {%4,%5,%6,%7}, {%8,%9}, {%0,%1,%2,%3};"
        : "+f"(d[0]), "+f"(d[1]), "+f"(d[2]), "+f"(d[3])
        : "r"(a[0]), "r"(a[1]), "r"(a[2]), "r"(a[3]), "r"(b[0]), "r"(b[1]));
}

// ---------------- kernel 1: projections (unchanged) ----------------
__global__ void proj_kernel(const float* __restrict__ x,
                            const float* __restrict__ ga_q_w, const float* __restrict__ ga_k_w,
                            const float* __restrict__ ga_v_w, const float* __restrict__ ga_lb_w,
                            const float* __restrict__ sa_q_w, const float* __restrict__ sa_k_w,
                            const float* __restrict__ sa_v_w, const float* __restrict__ sa_lb_w) {
    __shared__ float ws[20 * 64];
    int b = blockIdx.x, tid = threadIdx.x;
    int og = blockIdx.y >> 1, nh = blockIdx.y & 1;
    int n = nh * 128 + tid;

    for (int i = tid; i < 1280; i += 128) {
        int r = og * 20 + (i >> 6), c = i & 63;
        float v;
        if      (r < 8)   v = __ldg(&ga_q_w[r * 64 + c]);
        else if (r < 16)  v = __ldg(&ga_k_w[(r - 8) * 64 + c]);
        else if (r < 48)  v = __ldg(&ga_v_w[(r - 16) * 64 + c]);
        else if (r < 56)  v = __ldg(&sa_q_w[(r - 48) * 64 + c]);
        else if (r < 64)  v = __ldg(&sa_k_w[(r - 56) * 64 + c]);
        else if (r < 96)  v = __ldg(&sa_v_w[(r - 64) * 64 + c]);
        else if (r < 128) v = __ldg(&ga_lb_w[(r - 96) * 64 + c]);
        else              v = __ldg(&sa_lb_w[(r - 128) * 64 + c]);
        ws[i] = v;
    }
    __syncthreads();

    u64 xr2[32];
#pragma unroll
    for (int c = 0; c < 32; c++) {
        float a = __ldg(&x[b * 16384 + (2 * c) * 256 + n]);
        float bb = __ldg(&x[b * 16384 + (2 * c + 1) * 256 + n]);
        xr2[c] = f2pack(a, bb);
    }

    float* outp = g_proj + (b * 160 + og * 20) * 256 + n;
#pragma unroll 2
    for (int o = 0; o < 20; o++) {
        const ulonglong2* w2 = (const ulonglong2*)(ws + o * 64);
        u64 a0 = 0ULL, a1 = 0ULL;
#pragma unroll
        for (int i = 0; i < 16; i++) {
            ulonglong2 wv = w2[i];
            a0 = ffma2(wv.x, xr2[2 * i], a0);
            a1 = ffma2(wv.y, xr2[2 * i + 1], a1);
        }
        outp[o * 256] = hsum2(fadd2(a0, a1));
    }
}

// ---------------- kernel 2: attention (unchanged) ----------------
#define KS_OFF  0
#define VS_OFF  2048
#define MB_OFF  11264
#define MX_OFF  15616
#define EB_OFF  15872
#define STK_OFF 16128
#define ATTN_SMEM_BYTES (16384 * 4)

__global__ void attn_kernel(const int* __restrict__ stroke_idx,
                            const float* __restrict__ ga_v_b, const float* __restrict__ sa_v_b,
                            const float* __restrict__ ga_bn_p, const float* __restrict__ ga_lb_bn_p,
                            const float* __restrict__ sa_bn_p, const float* __restrict__ sa_lb_bn_p) {
    extern __shared__ float sm[];
    float* Ks   = sm + KS_OFF;
    float* Vs   = sm + VS_OFF;
    float* MB   = sm + MB_OFF;
    float* MX   = sm + MX_OFF;
    float* EB   = sm + EB_OFF;
    int*   stk  = (int*)(sm + STK_OFF);

    int b = blockIdx.x, tid = threadIdx.x;
    int branch = blockIdx.y >> 1, rh = blockIdx.y & 1;
    int row = tid & 127, mh = tid >> 7;
    int n = rh * 128 + row;
    int m0 = mh * 128;

    int qbase  = branch ? 48 : 0;
    int kbase  = qbase + 8;
    int vbase  = branch ? 64 : 16;
    int lbbase = branch ? 128 : 96;
    const float* vb = branch ? sa_v_b : ga_v_b;
    const float* gp = g_proj + b * 160 * 256;

    for (int i = tid; i < 2048; i += 256) {
        int r = i >> 8, m = i & 255;
        Ks[m * 8 + r] = gp[(kbase + r) * 256 + m];
    }
    for (int i = tid; i < 8192; i += 256) {
        int r = i >> 8, m = i & 255;
        Vs[m * 36 + r] = gp[(vbase + r) * 256 + m] + __ldg(vb + r);
    }
    if (branch)
        for (int i = tid; i < 256; i += 256) stk[i] = stroke_idx[b * 256 + i];
    __syncthreads();

    u64 q2[4];
#pragma unroll
    for (int j = 0; j < 4; j++)
        q2[j] = f2pack(gp[(qbase + 2 * j) * 256 + n], gp[(qbase + 2 * j + 1) * 256 + n]);

    const float INV_GA = 0.35355339059327373f;
    const float ESC    = 3.5355339059327378f;

    float mxl = -1e30f;
#pragma unroll 4
    for (int m = m0; m < m0 + 128; m++) {
        const ulonglong2* k2 = (const ulonglong2*)(Ks + m * 8);
        ulonglong2 ka = k2[0], kb = k2[1];
        u64 d0 = ffma2(q2[0], ka.x, 0ULL);
        d0 = ffma2(q2[1], ka.y, d0);
        d0 = ffma2(q2[2], kb.x, d0);
        d0 = ffma2(q2[3], kb.y, d0);
        mxl = fmaxf(mxl, hsum2(d0));
    }
    MX[tid] = mxl;
    __syncthreads();
    float mx = fmaxf(MX[row], MX[row + 128]);

    u64 o2[16];
#pragma unroll
    for (int v = 0; v < 16; v++) o2[v] = 0ULL;
    u64* mb64 = (u64*)MB;

    if (branch == 0) {
        float sum = 0.f;
#pragma unroll 2
        for (int m = m0; m < m0 + 128; m++) {
            const ulonglong2* k2 = (const ulonglong2*)(Ks + m * 8);
            ulonglong2 ka = k2[0], kb = k2[1];
            u64 d0 = ffma2(q2[0], ka.x, 0ULL);
            d0 = ffma2(q2[1], ka.y, d0);
            d0 = ffma2(q2[2], kb.x, d0);
            d0 = ffma2(q2[3], kb.y, d0);
            float e = __expf((hsum2(d0) - mx) * INV_GA);
            sum += e;
            u64 ep = f2pack(e, e);
            const ulonglong2* v2p = (const ulonglong2*)(Vs + m * 36);
#pragma unroll
            for (int g = 0; g < 8; g++) {
                ulonglong2 vv = v2p[g];
                o2[2 * g]     = ffma2(ep, vv.x, o2[2 * g]);
                o2[2 * g + 1] = ffma2(ep, vv.y, o2[2 * g + 1]);
            }
        }
        EB[tid] = sum;
        __syncthreads();
        float sumt = EB[row] + EB[row + 128];
        if (mh == 1) {
#pragma unroll
            for (int j = 0; j < 16; j++) mb64[row * 17 + j] = o2[j];
        }
        __syncthreads();
        if (mh == 0) {
            float rcp = 1.f / sumt;
#pragma unroll
            for (int g = 0; g < 16; g++) {
                o2[g] = fadd2(o2[g], mb64[row * 17 + g]);
                float v0, v1;
                unpack2(o2[g], v0, v1);
                int c0 = 2 * g;
                float sc1, sh1, sc2, sh2;
                bn_coef(ga_bn_p, c0, 32, sc1, sh1);
                bn_coef(ga_lb_bn_p, c0, 32, sc2, sh2);
                float lb0 = gp[(lbbase + c0) * 256 + n];
                g_f[b * 16384 + c0 * 256 + n] = fmaf(v0 * rcp, sc1, sh1) + fmaf(lb0, sc2, sh2);
                bn_coef(ga_bn_p, c0 + 1, 32, sc1, sh1);
                bn_coef(ga_lb_bn_p, c0 + 1, 32, sc2, sh2);
                float lb1 = gp[(lbbase + c0 + 1) * 256 + n];
                g_f[b * 16384 + (c0 + 1) * 256 + n] = fmaf(v1 * rcp, sc1, sh1) + fmaf(lb1, sc2, sh2);
            }
        }
    } else {
        const float CC  = 1.00001000005f;
        const float CM1 = 1.00000500002e-05f;
#pragma unroll
        for (int s = 0; s < 16; s++) MB[s * 256 + tid] = 0.f;
        __syncthreads();
        float E = 0.f;
#pragma unroll 2
        for (int m = m0; m < m0 + 128; m++) {
            const ulonglong2* k2 = (const ulonglong2*)(Ks + m * 8);
            ulonglong2 ka = k2[0], kb = k2[1];
            u64 d0 = ffma2(q2[0], ka.x, 0ULL);
            d0 = ffma2(q2[1], ka.y, d0);
            d0 = ffma2(q2[2], kb.x, d0);
            d0 = ffma2(q2[3], kb.y, d0);
            float e = __expf((hsum2(d0) - mx) * ESC);
            E += e;
            MB[stk[m] * 256 + tid] += e;
        }
        EB[tid] = E;
        __syncthreads();
        if (mh == 0) {
            float Et = EB[row] + EB[row + 128];
            float zi[16];
            float Sinv = 0.f;
#pragma unroll
            for (int s = 0; s < 16; s++) {
                float bsum = MB[s * 256 + row] + MB[s * 256 + row + 128];
                float z = fmaf(-CM1, bsum, CC * Et);
                zi[s] = 1.f / z;
                Sinv += zi[s];
            }
#pragma unroll
            for (int s = 0; s < 16; s++)
                MB[s * 256 + row] = fmaf(-CM1, zi[s], CC * Sinv);
        }
        __syncthreads();
#pragma unroll 2
        for (int m = m0; m < m0 + 128; m++) {
            const ulonglong2* k2 = (const ulonglong2*)(Ks + m * 8);
            ulonglong2 ka = k2[0], kb = k2[1];
            u64 d0 = ffma2(q2[0], ka.x, 0ULL);
            d0 = ffma2(q2[1], ka.y, d0);
            d0 = ffma2(q2[2], kb.x, d0);
            d0 = ffma2(q2[3], kb.y, d0);
            float e = __expf((hsum2(d0) - mx) * ESC);
            float w = e * MB[stk[m] * 256 + row];
            u64 wp = f2pack(w, w);
            const ulonglong2* v2p = (const ulonglong2*)(Vs + m * 36);
#pragma unroll
            for (int g = 0; g < 8; g++) {
                ulonglong2 vv = v2p[g];
                o2[2 * g]     = ffma2(wp, vv.x, o2[2 * g]);
                o2[2 * g + 1] = ffma2(wp, vv.y, o2[2 * g + 1]);
            }
        }
        __syncthreads();
        if (mh == 1) {
#pragma unroll
            for (int j = 0; j < 16; j++) mb64[row * 17 + j] = o2[j];
        }
        __syncthreads();
        if (mh == 0) {
#pragma unroll
            for (int g = 0; g < 16; g++) {
                o2[g] = fadd2(o2[g], mb64[row * 17 + g]);
                float v0, v1;
                unpack2(o2[g], v0, v1);
                int c0 = 2 * g;
                float sc1, sh1, sc2, sh2;
                bn_coef(sa_bn_p, c0, 32, sc1, sh1);
                bn_coef(sa_lb_bn_p, c0, 32, sc2, sh2);
                float lb0 = gp[(lbbase + c0) * 256 + n];
                g_f[b * 16384 + (32 + c0) * 256 + n] = fmaf(v0, sc1, sh1) + fmaf(lb0, sc2, sh2);
                bn_coef(sa_bn_p, c0 + 1, 32, sc1, sh1);
                bn_coef(sa_lb_bn_p, c0 + 1, 32, sc2, sh2);
                float lb1 = gp[(lbbase + c0 + 1) * 256 + n];
                g_f[b * 16384 + (32 + c0 + 1) * 256 + n] = fmaf(v1, sc1, sh1) + fmaf(lb1, sc2, sh2);
            }
        }
    }
}

// ---------------- kernel 3a: MLP stage 1 (unchanged) ----------------
#define M1_W_OFF 0
#define M1_F_OFF 4352
#define M1_SMEM_BYTES ((4352 + 8448) * 4)

__global__ void mlp1_kernel(const float* __restrict__ w1, const float* __restrict__ bn1) {
    extern __shared__ float sm[];
    float* w1s = sm + M1_W_OFF;
    float* fs  = sm + M1_F_OFF;

    int b = blockIdx.y, tid = threadIdx.x;
    int cc = blockIdx.x >> 1, nc = blockIdx.x & 1;
    int tx = tid & 31, ty = tid >> 5;

    for (int i = tid; i < 4096; i += 256) {
        int o = i >> 6, k = i & 63;
        w1s[k * 68 + o] = __ldg(&w1[(cc * 64 + o) * 64 + k]);
    }
    for (int i = tid; i < 8192; i += 256) {
        int k = i >> 7, col = i & 127;
        fs[k * 132 + col] = g_f[b * 16384 + k * 256 + nc * 128 + col];
    }
    __syncthreads();

    u64 acc[4][4];
#pragma unroll
    for (int p = 0; p < 4; p++)
#pragma unroll
        for (int c = 0; c < 4; c++) acc[p][c] = 0ULL;

#pragma unroll 4
    for (int k = 0; k < 64; k++) {
        const ulonglong2* wv2 = (const ulonglong2*)(w1s + k * 68 + ty * 8);
        ulonglong2 wa = wv2[0], wb = wv2[1];
        float4 hv = *(const float4*)(fs + k * 132 + tx * 4);
        u64 h0 = f2pack(hv.x, hv.x), h1 = f2pack(hv.y, hv.y);
        u64 h2 = f2pack(hv.z, hv.z), h3 = f2pack(hv.w, hv.w);
        acc[0][0] = ffma2(wa.x, h0, acc[0][0]);
        acc[0][1] = ffma2(wa.x, h1, acc[0][1]);
        acc[0][2] = ffma2(wa.x, h2, acc[0][2]);
        acc[0][3] = ffma2(wa.x, h3, acc[0][3]);
        acc[1][0] = ffma2(wa.y, h0, acc[1][0]);
        acc[1][1] = ffma2(wa.y, h1, acc[1][1]);
        acc[1][2] = ffma2(wa.y, h2, acc[1][2]);
        acc[1][3] = ffma2(wa.y, h3, acc[1][3]);
        acc[2][0] = ffma2(wb.x, h0, acc[2][0]);
        acc[2][1] = ffma2(wb.x, h1, acc[2][1]);
        acc[2][2] = ffma2(wb.x, h2, acc[2][2]);
        acc[2][3] = ffma2(wb.x, h3, acc[2][3]);
        acc[3][0] = ffma2(wb.y, h0, acc[3][0]);
        acc[3][1] = ffma2(wb.y, h1, acc[3][1]);
        acc[3][2] = ffma2(wb.y, h2, acc[3][2]);
        acc[3][3] = ffma2(wb.y, h3, acc[3][3]);
    }

    int n0 = nc * 128 + tx * 4;
#pragma unroll
    for (int p = 0; p < 4; p++) {
        int ch0 = cc * 64 + ty * 8 + 2 * p;
        float sc0, sh0, sc1s, sh1s;
        bn_coef(bn1, ch0, 256, sc0, sh0);
        bn_coef(bn1, ch0 + 1, 256, sc1s, sh1s);
        float4 r0, r1;
        float a, bb;
        unpack2(acc[p][0], a, bb); r0.x = fmaxf(fmaf(a, sc0, sh0), 0.f); r1.x = fmaxf(fmaf(bb, sc1s, sh1s), 0.f);
        unpack2(acc[p][1], a, bb); r0.y = fmaxf(fmaf(a, sc0, sh0), 0.f); r1.y = fmaxf(fmaf(bb, sc1s, sh1s), 0.f);
        unpack2(acc[p][2], a, bb); r0.z = fmaxf(fmaf(a, sc0, sh0), 0.f); r1.z = fmaxf(fmaf(bb, sc1s, sh1s), 0.f);
        unpack2(acc[p][3], a, bb); r0.w = fmaxf(fmaf(a, sc0, sh0), 0.f); r1.w = fmaxf(fmaf(bb, sc1s, sh1s), 0.f);
        *(float4*)&g_h[b * 65536 + ch0 * 256 + n0]       = r0;
        *(float4*)&g_h[b * 65536 + (ch0 + 1) * 256 + n0] = r1;
    }
}

// ---------------- kernel 3b-pre: transpose + bf16 hi/lo split of h (and w2) ----------------
// grid (17, 64), block 256. bx<16: 16-o x 256-n tile transpose; bx==16,by==0: w2 split.
__global__ void hconv_kernel(const float* __restrict__ w2) {
    int bx = blockIdx.x, b = blockIdx.y, tid = threadIdx.x;
    if (bx == 16) {
        if (b == 0) {
            for (int i = tid; i < 16384; i += 256) {
                float v = __ldg(&w2[i]);
                __nv_bfloat16 h = __float2bfloat16(v);
                g_w2h[i] = h;
                g_w2l[i] = __float2bfloat16(v - __bfloat162float(h));
            }
        }
        return;
    }
    __shared__ float s[16 * 257];
    int o0 = bx * 16;
    for (int i = tid; i < 4096; i += 256) {
        int oo = i >> 8, n = i & 255;
        s[oo * 257 + n] = g_h[b * 65536 + (o0 + oo) * 256 + n];
    }
    __syncthreads();
    int n = tid;
    unsigned int hh[8], hl[8];
#pragma unroll
    for (int j = 0; j < 8; j++) {
        float v0 = s[(2 * j) * 257 + n];
        float v1 = s[(2 * j + 1) * 257 + n];
        __nv_bfloat16 h0 = __float2bfloat16(v0), h1 = __float2bfloat16(v1);
        __nv_bfloat16 l0 = __float2bfloat16(v0 - __bfloat162float(h0));
        __nv_bfloat16 l1 = __float2bfloat16(v1 - __bfloat162float(h1));
        hh[j] = (unsigned int)__bfloat16_as_ushort(h0) | ((unsigned int)__bfloat16_as_ushort(h1) << 16);
        hl[j] = (unsigned int)__bfloat16_as_ushort(l0) | ((unsigned int)__bfloat16_as_ushort(l1) << 16);
    }
    unsigned int* ph = (unsigned int*)g_hh + b * 32768 + n * 128 + o0 / 2;
    unsigned int* pl = (unsigned int*)g_hl + b * 32768 + n * 128 + o0 / 2;
    *(uint4*)(ph)     = make_uint4(hh[0], hh[1], hh[2], hh[3]);
    *(uint4*)(ph + 4) = make_uint4(hh[4], hh[5], hh[6], hh[7]);
    *(uint4*)(pl)     = make_uint4(hl[0], hl[1], hl[2], hl[3]);
    *(uint4*)(pl + 4) = make_uint4(hl[4], hl[5], hl[6], hl[7]);
}

// ---------------- kernel 3b: MLP stage 2 via mma.sync (bf16 hi/lo, 3 terms) ----------------
// grid (2, 64): bx = n-half (128). block 256 = 8 warps; warp tile 32ch x 32n.
// D[c][n] = sum_k w2[c][k] * h'[n][k]; A = w2 (row-major), B = h' (col-major frag).
__global__ void mlp2_mma_kernel(const float* __restrict__ bn2, float* __restrict__ out) {
    __shared__ float scs[64], shs[64];
    int tid = threadIdx.x;
    int b = blockIdx.y;
    if (tid < 64) {
        float sc, sh;
        bn_coef(bn2, tid, 64, sc, sh);
        scs[tid] = sc;
        shs[tid] = sh;
    }
    __syncthreads();

    int w = tid >> 5, lane = tid & 31;
    int g = lane >> 2, tg = lane & 3;
    int cbase = (w & 1) * 32;
    int nbase = blockIdx.x * 128 + (w >> 1) * 32;

    const __nv_bfloat16* hh = g_hh + (size_t)b * 65536;
    const __nv_bfloat16* hl = g_hl + (size_t)b * 65536;

    float d[2][4][4];
#pragma unroll
    for (int cs = 0; cs < 2; cs++)
#pragma unroll
        for (int ns = 0; ns < 4; ns++)
#pragma unroll
            for (int j = 0; j < 4; j++) d[cs][ns][j] = 0.f;

    for (int k0 = 0; k0 < 256; k0 += 16) {
        unsigned int ah[2][4], al[2][4], bh[4][2], bl[4][2];
#pragma unroll
        for (int cs = 0; cs < 2; cs++) {
            int r0 = (cbase + cs * 16 + g) * 256 + k0 + 2 * tg;
            int r1 = r0 + 8 * 256;
            ah[cs][0] = __ldg((const unsigned int*)(g_w2h + r0));
            ah[cs][1] = __ldg((const unsigned int*)(g_w2h + r1));
            ah[cs][2] = __ldg((const unsigned int*)(g_w2h + r0 + 8));
            ah[cs][3] = __ldg((const unsigned int*)(g_w2h + r1 + 8));
            al[cs][0] = __ldg((const unsigned int*)(g_w2l + r0));
            al[cs][1] = __ldg((const unsigned int*)(g_w2l + r1));
            al[cs][2] = __ldg((const unsigned int*)(g_w2l + r0 + 8));
            al[cs][3] = __ldg((const unsigned int*)(g_w2l + r1 + 8));
        }
#pragma unroll
        for (int ns = 0; ns < 4; ns++) {
            int rb = (nbase + ns * 8 + g) * 256 + k0 + 2 * tg;
            bh[ns][0] = __ldg((const unsigned int*)(hh + rb));
            bh[ns][1] = __ldg((const unsigned int*)(hh + rb + 8));
            bl[ns][0] = __ldg((const unsigned int*)(hl + rb));
            bl[ns][1] = __ldg((const unsigned int*)(hl + rb + 8));
        }
#pragma unroll
        for (int cs = 0; cs < 2; cs++)
#pragma unroll
            for (int ns = 0; ns < 4; ns++) {
                mma_bf16(d[cs][ns], ah[cs], bh[ns]);   // hi*hi
                mma_bf16(d[cs][ns], al[cs], bh[ns]);   // lo*hi
                mma_bf16(d[cs][ns], ah[cs], bl[ns]);   // hi*lo
            }
    }

    // epilogue: bn2 + residual + relu
#pragma unroll
    for (int cs = 0; cs < 2; cs++) {
        int c0r = cbase + cs * 16 + g;
        int c1r = c0r + 8;
        float sc0 = scs[c0r], sh0 = shs[c0r];
        float sc1 = scs[c1r], sh1 = shs[c1r];
#pragma unroll
        for (int ns = 0; ns < 4; ns++) {
            int n = nbase + ns * 8 + 2 * tg;
            const float* dd = d[cs][ns];
            float2 f0 = *(const float2*)&g_f[b * 16384 + c0r * 256 + n];
            float2 f1 = *(const float2*)&g_f[b * 16384 + c1r * 256 + n];
            float2 r0, r1;
            r0.x = fmaxf(fmaf(dd[0], sc0, sh0) + f0.x, 0.f);
            r0.y = fmaxf(fmaf(dd[1], sc0, sh0) + f0.y, 0.f);
            r1.x = fmaxf(fmaf(dd[2], sc1, sh1) + f1.x, 0.f);
            r1.y = fmaxf(fmaf(dd[3], sc1, sh1) + f1.y, 0.f);
            *(float2*)&out[b * 16384 + c0r * 256 + n] = r0;
            *(float2*)&out[b * 16384 + c1r * 256 + n] = r1;
        }
    }
}

// ---------------- launch ----------------
extern "C" void kernel_launch(void* const* d_in, const int* in_sizes, int n_in,
                              void* d_out, int out_size) {
    int base = (in_sizes[2] == 512) ? 2 : 3;

    const float* x          = (const float*)d_in[0];
    const int*   stroke     = (const int*)d_in[1];
    const float* ga_q_w     = (const float*)d_in[base + 0];
    const float* ga_k_w     = (const float*)d_in[base + 1];
    const float* ga_v_w     = (const float*)d_in[base + 2];
    const float* ga_v_b     = (const float*)d_in[base + 3];
    const float* ga_bn_p    = (const float*)d_in[base + 4];
    const float* ga_lb_w    = (const float*)d_in[base + 5];
    const float* ga_lb_bn_p = (const float*)d_in[base + 6];
    const float* sa_q_w     = (const float*)d_in[base + 7];
    const float* sa_k_w     = (const float*)d_in[base + 8];
    const float* sa_v_w     = (const float*)d_in[base + 9];
    const float* sa_v_b     = (const float*)d_in[base + 10];
    const float* sa_bn_p    = (const float*)d_in[base + 11];
    const float* sa_lb_w    = (const float*)d_in[base + 12];
    const float* sa_lb_bn_p = (const float*)d_in[base + 13];
    const float* mlp_w1     = (const float*)d_in[base + 14];
    const float* mlp_bn1_p  = (const float*)d_in[base + 15];
    const float* mlp_w2     = (const float*)d_in[base + 16];
    const float* mlp_bn2_p  = (const float*)d_in[base + 17];

    cudaFuncSetAttribute(attn_kernel, cudaFuncAttributeMaxDynamicSharedMemorySize, ATTN_SMEM_BYTES);
    cudaFuncSetAttribute(mlp1_kernel, cudaFuncAttributeMaxDynamicSharedMemorySize, M1_SMEM_BYTES);

    proj_kernel<<<dim3(64, 16), 128>>>(x, ga_q_w, ga_k_w, ga_v_w, ga_lb_w,
                                       sa_q_w, sa_k_w, sa_v_w, sa_lb_w);
    attn_kernel<<<dim3(64, 4), 256, ATTN_SMEM_BYTES>>>(stroke, ga_v_b, sa_v_b,
                                                       ga_bn_p, ga_lb_bn_p,
                                                       sa_bn_p, sa_lb_bn_p);
    mlp1_kernel<<<dim3(8, 64), 256, M1_SMEM_BYTES>>>(mlp_w1, mlp_bn1_p);
    hconv_kernel<<<dim3(17, 64), 256>>>(mlp_w2);
    mlp2_mma_kernel<<<dim3(2, 64), 256>>>(mlp_bn2_p, (float*)d_out);
}

// round 13
// speedup vs baseline: 1.0515x; 1.0515x over previous
#include <cuda_runtime.h>
#include <cuda_bf16.h>
#include <math.h>

#define BATCH 64
#define CH    64
#define NPT   256

typedef unsigned long long u64;

// ---------------- global scratch ----------------
__device__ float g_proj[BATCH * 160 * NPT];
__device__ float g_f[BATCH * CH * NPT];            // [b][ch][n]
__device__ __nv_bfloat16 g_hh[BATCH * NPT * 256];  // [b][n][o] hi
__device__ __nv_bfloat16 g_hl[BATCH * NPT * 256];  // [b][n][o] lo
__device__ __nv_bfloat16 g_w2h[64 * 256];
__device__ __nv_bfloat16 g_w2l[64 * 256];

// ---------------- f32x2 helpers ----------------
__device__ __forceinline__ u64 f2pack(float a, float b) {
    u64 r;
    asm("mov.b64 %0, {%1, %2};" : "=l"(r) : "r"(__float_as_uint(a)), "r"(__float_as_uint(b)));
    return r;
}
__device__ __forceinline__ u64 ffma2(u64 a, u64 b, u64 c) {
    u64 d;
    asm("fma.rn.f32x2 %0, %1, %2, %3;" : "=l"(d) : "l"(a), "l"(b), "l"(c));
    return d;
}
__device__ __forceinline__ u64 fadd2(u64 a, u64 b) {
    u64 d;
    asm("add.rn.f32x2 %0, %1, %2;" : "=l"(d) : "l"(a), "l"(b));
    return d;
}
__device__ __forceinline__ void unpack2(u64 v, float& lo, float& hi) {
    unsigned int l, h;
    asm("mov.b64 {%0, %1}, %2;" : "=r"(l), "=r"(h) : "l"(v));
    lo = __uint_as_float(l);
    hi = __uint_as_float(h);
}
__device__ __forceinline__ float hsum2(u64 v) {
    float lo, hi;
    unpack2(v, lo, hi);
    return lo + hi;
}
__device__ __forceinline__ void bn_coef(const float* __restrict__ p, int ch, int cn,
                                        float& sc, float& sh) {
    float ga = __ldg(p + ch);
    float be = __ldg(p + cn + ch);
    float mu = __ldg(p + 2 * cn + ch);
    float va = __ldg(p + 3 * cn + ch);
    sc = ga * rsqrtf(va + 1e-5f);
    sh = fmaf(-mu, sc, be);
}

// mma.sync m16n8k16 bf16: d += a @ b
__device__ __forceinline__ void mma_bf16(float* d, const unsigned int* a, const unsigned int* b) {
    asm volatile("mma.sync.aligned.m16n8k16.row.col.f32.bf16.bf16.f32 "
        "{%0,%1,%2,%3}, {%4,%5,%6,%7}, {%8,%9}, {%0,%1,%2,%3};"
        : "+f"(d[0]), "+f"(d[1]), "+f"(d[2]), "+f"(d[3])
        : "r"(a[0]), "r"(a[1]), "r"(a[2]), "r"(a[3]), "r"(b[0]), "r"(b[1]));
}

// ---------------- kernel 1: projections (unchanged) ----------------
__global__ void proj_kernel(const float* __restrict__ x,
                            const float* __restrict__ ga_q_w, const float* __restrict__ ga_k_w,
                            const float* __restrict__ ga_v_w, const float* __restrict__ ga_lb_w,
                            const float* __restrict__ sa_q_w, const float* __restrict__ sa_k_w,
                            const float* __restrict__ sa_v_w, const float* __restrict__ sa_lb_w) {
    __shared__ float ws[20 * 64];
    int b = blockIdx.x, tid = threadIdx.x;
    int og = blockIdx.y >> 1, nh = blockIdx.y & 1;
    int n = nh * 128 + tid;

    for (int i = tid; i < 1280; i += 128) {
        int r = og * 20 + (i >> 6), c = i & 63;
        float v;
        if      (r < 8)   v = __ldg(&ga_q_w[r * 64 + c]);
        else if (r < 16)  v = __ldg(&ga_k_w[(r - 8) * 64 + c]);
        else if (r < 48)  v = __ldg(&ga_v_w[(r - 16) * 64 + c]);
        else if (r < 56)  v = __ldg(&sa_q_w[(r - 48) * 64 + c]);
        else if (r < 64)  v = __ldg(&sa_k_w[(r - 56) * 64 + c]);
        else if (r < 96)  v = __ldg(&sa_v_w[(r - 64) * 64 + c]);
        else if (r < 128) v = __ldg(&ga_lb_w[(r - 96) * 64 + c]);
        else              v = __ldg(&sa_lb_w[(r - 128) * 64 + c]);
        ws[i] = v;
    }
    __syncthreads();

    u64 xr2[32];
#pragma unroll
    for (int c = 0; c < 32; c++) {
        float a = __ldg(&x[b * 16384 + (2 * c) * 256 + n]);
        float bb = __ldg(&x[b * 16384 + (2 * c + 1) * 256 + n]);
        xr2[c] = f2pack(a, bb);
    }

    float* outp = g_proj + (b * 160 + og * 20) * 256 + n;
#pragma unroll 2
    for (int o = 0; o < 20; o++) {
        const ulonglong2* w2 = (const ulonglong2*)(ws + o * 64);
        u64 a0 = 0ULL, a1 = 0ULL;
#pragma unroll
        for (int i = 0; i < 16; i++) {
            ulonglong2 wv = w2[i];
            a0 = ffma2(wv.x, xr2[2 * i], a0);
            a1 = ffma2(wv.y, xr2[2 * i + 1], a1);
        }
        outp[o * 256] = hsum2(fadd2(a0, a1));
    }
}

// ---------------- kernel 2: attention (unchanged) ----------------
#define KS_OFF  0
#define VS_OFF  2048
#define MB_OFF  11264
#define MX_OFF  15616
#define EB_OFF  15872
#define STK_OFF 16128
#define ATTN_SMEM_BYTES (16384 * 4)

__global__ void attn_kernel(const int* __restrict__ stroke_idx,
                            const float* __restrict__ ga_v_b, const float* __restrict__ sa_v_b,
                            const float* __restrict__ ga_bn_p, const float* __restrict__ ga_lb_bn_p,
                            const float* __restrict__ sa_bn_p, const float* __restrict__ sa_lb_bn_p) {
    extern __shared__ float sm[];
    float* Ks   = sm + KS_OFF;
    float* Vs   = sm + VS_OFF;
    float* MB   = sm + MB_OFF;
    float* MX   = sm + MX_OFF;
    float* EB   = sm + EB_OFF;
    int*   stk  = (int*)(sm + STK_OFF);

    int b = blockIdx.x, tid = threadIdx.x;
    int branch = blockIdx.y >> 1, rh = blockIdx.y & 1;
    int row = tid & 127, mh = tid >> 7;
    int n = rh * 128 + row;
    int m0 = mh * 128;

    int qbase  = branch ? 48 : 0;
    int kbase  = qbase + 8;
    int vbase  = branch ? 64 : 16;
    int lbbase = branch ? 128 : 96;
    const float* vb = branch ? sa_v_b : ga_v_b;
    const float* gp = g_proj + b * 160 * 256;

    for (int i = tid; i < 2048; i += 256) {
        int r = i >> 8, m = i & 255;
        Ks[m * 8 + r] = gp[(kbase + r) * 256 + m];
    }
    for (int i = tid; i < 8192; i += 256) {
        int r = i >> 8, m = i & 255;
        Vs[m * 36 + r] = gp[(vbase + r) * 256 + m] + __ldg(vb + r);
    }
    if (branch)
        for (int i = tid; i < 256; i += 256) stk[i] = stroke_idx[b * 256 + i];
    __syncthreads();

    u64 q2[4];
#pragma unroll
    for (int j = 0; j < 4; j++)
        q2[j] = f2pack(gp[(qbase + 2 * j) * 256 + n], gp[(qbase + 2 * j + 1) * 256 + n]);

    const float INV_GA = 0.35355339059327373f;
    const float ESC    = 3.5355339059327378f;

    float mxl = -1e30f;
#pragma unroll 4
    for (int m = m0; m < m0 + 128; m++) {
        const ulonglong2* k2 = (const ulonglong2*)(Ks + m * 8);
        ulonglong2 ka = k2[0], kb = k2[1];
        u64 d0 = ffma2(q2[0], ka.x, 0ULL);
        d0 = ffma2(q2[1], ka.y, d0);
        d0 = ffma2(q2[2], kb.x, d0);
        d0 = ffma2(q2[3], kb.y, d0);
        mxl = fmaxf(mxl, hsum2(d0));
    }
    MX[tid] = mxl;
    __syncthreads();
    float mx = fmaxf(MX[row], MX[row + 128]);

    u64 o2[16];
#pragma unroll
    for (int v = 0; v < 16; v++) o2[v] = 0ULL;
    u64* mb64 = (u64*)MB;

    if (branch == 0) {
        float sum = 0.f;
#pragma unroll 2
        for (int m = m0; m < m0 + 128; m++) {
            const ulonglong2* k2 = (const ulonglong2*)(Ks + m * 8);
            ulonglong2 ka = k2[0], kb = k2[1];
            u64 d0 = ffma2(q2[0], ka.x, 0ULL);
            d0 = ffma2(q2[1], ka.y, d0);
            d0 = ffma2(q2[2], kb.x, d0);
            d0 = ffma2(q2[3], kb.y, d0);
            float e = __expf((hsum2(d0) - mx) * INV_GA);
            sum += e;
            u64 ep = f2pack(e, e);
            const ulonglong2* v2p = (const ulonglong2*)(Vs + m * 36);
#pragma unroll
            for (int g = 0; g < 8; g++) {
                ulonglong2 vv = v2p[g];
                o2[2 * g]     = ffma2(ep, vv.x, o2[2 * g]);
                o2[2 * g + 1] = ffma2(ep, vv.y, o2[2 * g + 1]);
            }
        }
        EB[tid] = sum;
        __syncthreads();
        float sumt = EB[row] + EB[row + 128];
        if (mh == 1) {
#pragma unroll
            for (int j = 0; j < 16; j++) mb64[row * 17 + j] = o2[j];
        }
        __syncthreads();
        if (mh == 0) {
            float rcp = 1.f / sumt;
#pragma unroll
            for (int g = 0; g < 16; g++) {
                o2[g] = fadd2(o2[g], mb64[row * 17 + g]);
                float v0, v1;
                unpack2(o2[g], v0, v1);
                int c0 = 2 * g;
                float sc1, sh1, sc2, sh2;
                bn_coef(ga_bn_p, c0, 32, sc1, sh1);
                bn_coef(ga_lb_bn_p, c0, 32, sc2, sh2);
                float lb0 = gp[(lbbase + c0) * 256 + n];
                g_f[b * 16384 + c0 * 256 + n] = fmaf(v0 * rcp, sc1, sh1) + fmaf(lb0, sc2, sh2);
                bn_coef(ga_bn_p, c0 + 1, 32, sc1, sh1);
                bn_coef(ga_lb_bn_p, c0 + 1, 32, sc2, sh2);
                float lb1 = gp[(lbbase + c0 + 1) * 256 + n];
                g_f[b * 16384 + (c0 + 1) * 256 + n] = fmaf(v1 * rcp, sc1, sh1) + fmaf(lb1, sc2, sh2);
            }
        }
    } else {
        const float CC  = 1.00001000005f;
        const float CM1 = 1.00000500002e-05f;
#pragma unroll
        for (int s = 0; s < 16; s++) MB[s * 256 + tid] = 0.f;
        __syncthreads();
        float E = 0.f;
#pragma unroll 2
        for (int m = m0; m < m0 + 128; m++) {
            const ulonglong2* k2 = (const ulonglong2*)(Ks + m * 8);
            ulonglong2 ka = k2[0], kb = k2[1];
            u64 d0 = ffma2(q2[0], ka.x, 0ULL);
            d0 = ffma2(q2[1], ka.y, d0);
            d0 = ffma2(q2[2], kb.x, d0);
            d0 = ffma2(q2[3], kb.y, d0);
            float e = __expf((hsum2(d0) - mx) * ESC);
            E += e;
            MB[stk[m] * 256 + tid] += e;
        }
        EB[tid] = E;
        __syncthreads();
        if (mh == 0) {
            float Et = EB[row] + EB[row + 128];
            float zi[16];
            float Sinv = 0.f;
#pragma unroll
            for (int s = 0; s < 16; s++) {
                float bsum = MB[s * 256 + row] + MB[s * 256 + row + 128];
                float z = fmaf(-CM1, bsum, CC * Et);
                zi[s] = 1.f / z;
                Sinv += zi[s];
            }
#pragma unroll
            for (int s = 0; s < 16; s++)
                MB[s * 256 + row] = fmaf(-CM1, zi[s], CC * Sinv);
        }
        __syncthreads();
#pragma unroll 2
        for (int m = m0; m < m0 + 128; m++) {
            const ulonglong2* k2 = (const ulonglong2*)(Ks + m * 8);
            ulonglong2 ka = k2[0], kb = k2[1];
            u64 d0 = ffma2(q2[0], ka.x, 0ULL);
            d0 = ffma2(q2[1], ka.y, d0);
            d0 = ffma2(q2[2], kb.x, d0);
            d0 = ffma2(q2[3], kb.y, d0);
            float e = __expf((hsum2(d0) - mx) * ESC);
            float w = e * MB[stk[m] * 256 + row];
            u64 wp = f2pack(w, w);
            const ulonglong2* v2p = (const ulonglong2*)(Vs + m * 36);
#pragma unroll
            for (int g = 0; g < 8; g++) {
                ulonglong2 vv = v2p[g];
                o2[2 * g]     = ffma2(wp, vv.x, o2[2 * g]);
                o2[2 * g + 1] = ffma2(wp, vv.y, o2[2 * g + 1]);
            }
        }
        __syncthreads();
        if (mh == 1) {
#pragma unroll
            for (int j = 0; j < 16; j++) mb64[row * 17 + j] = o2[j];
        }
        __syncthreads();
        if (mh == 0) {
#pragma unroll
            for (int g = 0; g < 16; g++) {
                o2[g] = fadd2(o2[g], mb64[row * 17 + g]);
                float v0, v1;
                unpack2(o2[g], v0, v1);
                int c0 = 2 * g;
                float sc1, sh1, sc2, sh2;
                bn_coef(sa_bn_p, c0, 32, sc1, sh1);
                bn_coef(sa_lb_bn_p, c0, 32, sc2, sh2);
                float lb0 = gp[(lbbase + c0) * 256 + n];
                g_f[b * 16384 + (32 + c0) * 256 + n] = fmaf(v0, sc1, sh1) + fmaf(lb0, sc2, sh2);
                bn_coef(sa_bn_p, c0 + 1, 32, sc1, sh1);
                bn_coef(sa_lb_bn_p, c0 + 1, 32, sc2, sh2);
                float lb1 = gp[(lbbase + c0 + 1) * 256 + n];
                g_f[b * 16384 + (32 + c0 + 1) * 256 + n] = fmaf(v1, sc1, sh1) + fmaf(lb1, sc2, sh2);
            }
        }
    }
}

// ---------------- kernel 3a: MLP stage 1 + fused transpose/split epilogue ----------------
// grid (8, 64): bx>>1 = ch chunk (64 of 256), bx&1 = col chunk (128). block 256.
// Writes g_hh/g_hl [b][n][o] bf16 directly (no fp32 g_h, no separate transpose kernel).
#define M1_W_OFF 0
#define M1_F_OFF 4352
#define M1_SMEM_BYTES ((4352 + 8448) * 4)   // >= 128*68 floats for ts reuse

__global__ void mlp1_kernel(const float* __restrict__ w1, const float* __restrict__ bn1) {
    extern __shared__ float sm[];
    float* w1s = sm + M1_W_OFF;
    float* fs  = sm + M1_F_OFF;

    int b = blockIdx.y, tid = threadIdx.x;
    int cc = blockIdx.x >> 1, nc = blockIdx.x & 1;
    int tx = tid & 31, ty = tid >> 5;

    for (int i = tid; i < 4096; i += 256) {
        int o = i >> 6, k = i & 63;
        w1s[k * 68 + o] = __ldg(&w1[(cc * 64 + o) * 64 + k]);
    }
    for (int i = tid; i < 8192; i += 256) {
        int k = i >> 7, col = i & 127;
        fs[k * 132 + col] = g_f[b * 16384 + k * 256 + nc * 128 + col];
    }
    __syncthreads();

    u64 acc[4][4];
#pragma unroll
    for (int p = 0; p < 4; p++)
#pragma unroll
        for (int c = 0; c < 4; c++) acc[p][c] = 0ULL;

#pragma unroll 4
    for (int k = 0; k < 64; k++) {
        const ulonglong2* wv2 = (const ulonglong2*)(w1s + k * 68 + ty * 8);
        ulonglong2 wa = wv2[0], wb = wv2[1];
        float4 hv = *(const float4*)(fs + k * 132 + tx * 4);
        u64 h0 = f2pack(hv.x, hv.x), h1 = f2pack(hv.y, hv.y);
        u64 h2 = f2pack(hv.z, hv.z), h3 = f2pack(hv.w, hv.w);
        acc[0][0] = ffma2(wa.x, h0, acc[0][0]);
        acc[0][1] = ffma2(wa.x, h1, acc[0][1]);
        acc[0][2] = ffma2(wa.x, h2, acc[0][2]);
        acc[0][3] = ffma2(wa.x, h3, acc[0][3]);
        acc[1][0] = ffma2(wa.y, h0, acc[1][0]);
        acc[1][1] = ffma2(wa.y, h1, acc[1][1]);
        acc[1][2] = ffma2(wa.y, h2, acc[1][2]);
        acc[1][3] = ffma2(wa.y, h3, acc[1][3]);
        acc[2][0] = ffma2(wb.x, h0, acc[2][0]);
        acc[2][1] = ffma2(wb.x, h1, acc[2][1]);
        acc[2][2] = ffma2(wb.x, h2, acc[2][2]);
        acc[2][3] = ffma2(wb.x, h3, acc[2][3]);
        acc[3][0] = ffma2(wb.y, h0, acc[3][0]);
        acc[3][1] = ffma2(wb.y, h1, acc[3][1]);
        acc[3][2] = ffma2(wb.y, h2, acc[3][2]);
        acc[3][3] = ffma2(wb.y, h3, acc[3][3]);
    }

    // stage h in smem transposed: ts[col_local][ch_local], stride 68
    __syncthreads();    // all fs/w1s reads done
    float* ts = sm;     // 128*68 floats = 34.8 KB
#pragma unroll
    for (int p = 0; p < 4; p++) {
        int ch0 = cc * 64 + ty * 8 + 2 * p;
        float sc0, sh0, sc1s, sh1s;
        bn_coef(bn1, ch0, 256, sc0, sh0);
        bn_coef(bn1, ch0 + 1, 256, sc1s, sh1s);
        int chl = ty * 8 + 2 * p;
#pragma unroll
        for (int c = 0; c < 4; c++) {
            float a, bb;
            unpack2(acc[p][c], a, bb);
            int col = tx * 4 + c;
            ts[col * 68 + chl]     = fmaxf(fmaf(a, sc0, sh0), 0.f);
            ts[col * 68 + chl + 1] = fmaxf(fmaf(bb, sc1s, sh1s), 0.f);
        }
    }
    __syncthreads();

    // convert + write bf16 hi/lo, coalesced uint4 stores
    for (int i = tid; i < 2048; i += 256) {
        int sel = i >> 10, rr = i & 1023;
        int nl = rr >> 3, ck = rr & 7;
        const float* src = ts + nl * 68 + ck * 8;
        unsigned int wds[4];
#pragma unroll
        for (int j = 0; j < 4; j++) {
            float v0 = src[2 * j], v1 = src[2 * j + 1];
            __nv_bfloat16 h0 = __float2bfloat16(v0), h1 = __float2bfloat16(v1);
            if (sel) {
                __nv_bfloat16 l0 = __float2bfloat16(v0 - __bfloat162float(h0));
                __nv_bfloat16 l1 = __float2bfloat16(v1 - __bfloat162float(h1));
                wds[j] = (unsigned int)__bfloat16_as_ushort(l0) | ((unsigned int)__bfloat16_as_ushort(l1) << 16);
            } else {
                wds[j] = (unsigned int)__bfloat16_as_ushort(h0) | ((unsigned int)__bfloat16_as_ushort(h1) << 16);
            }
        }
        __nv_bfloat16* dst = (sel ? g_hl : g_hh) + (size_t)b * 65536
                           + (size_t)(nc * 128 + nl) * 256 + cc * 64 + ck * 8;
        *(uint4*)dst = make_uint4(wds[0], wds[1], wds[2], wds[3]);
    }
}

// ---------------- w2 split (tiny) ----------------
__global__ void w2split_kernel(const float* __restrict__ w2) {
    int i = blockIdx.x * 2048 + threadIdx.x;
#pragma unroll
    for (int j = 0; j < 8; j++, i += 256) {
        float v = __ldg(&w2[i]);
        __nv_bfloat16 h = __float2bfloat16(v);
        g_w2h[i] = h;
        g_w2l[i] = __float2bfloat16(v - __bfloat162float(h));
    }
}

// ---------------- kernel 3b: MLP stage 2 via mma.sync ----------------
// grid (4, 64): bx = n chunk (64). block 128 = 4 warps; warp tile 32ch x 32n.
__global__ void mlp2_mma_kernel(const float* __restrict__ bn2, float* __restrict__ out) {
    __shared__ float scs[64], shs[64];
    int tid = threadIdx.x;
    int b = blockIdx.y;
    if (tid < 64) {
        float sc, sh;
        bn_coef(bn2, tid, 64, sc, sh);
        scs[tid] = sc;
        shs[tid] = sh;
    }
    __syncthreads();

    int w = tid >> 5, lane = tid & 31;
    int g = lane >> 2, tg = lane & 3;
    int cbase = (w & 1) * 32;
    int nbase = blockIdx.x * 64 + (w >> 1) * 32;

    const __nv_bfloat16* hh = g_hh + (size_t)b * 65536;
    const __nv_bfloat16* hl = g_hl + (size_t)b * 65536;

    float d[2][4][4];
#pragma unroll
    for (int cs = 0; cs < 2; cs++)
#pragma unroll
        for (int ns = 0; ns < 4; ns++)
#pragma unroll
            for (int j = 0; j < 4; j++) d[cs][ns][j] = 0.f;

    for (int k0 = 0; k0 < 256; k0 += 16) {
        unsigned int ah[2][4], al[2][4], bh[4][2], bl[4][2];
#pragma unroll
        for (int cs = 0; cs < 2; cs++) {
            int r0 = (cbase + cs * 16 + g) * 256 + k0 + 2 * tg;
            int r1 = r0 + 8 * 256;
            ah[cs][0] = __ldg((const unsigned int*)(g_w2h + r0));
            ah[cs][1] = __ldg((const unsigned int*)(g_w2h + r1));
            ah[cs][2] = __ldg((const unsigned int*)(g_w2h + r0 + 8));
            ah[cs][3] = __ldg((const unsigned int*)(g_w2h + r1 + 8));
            al[cs][0] = __ldg((const unsigned int*)(g_w2l + r0));
            al[cs][1] = __ldg((const unsigned int*)(g_w2l + r1));
            al[cs][2] = __ldg((const unsigned int*)(g_w2l + r0 + 8));
            al[cs][3] = __ldg((const unsigned int*)(g_w2l + r1 + 8));
        }
#pragma unroll
        for (int ns = 0; ns < 4; ns++) {
            int rb = (nbase + ns * 8 + g) * 256 + k0 + 2 * tg;
            bh[ns][0] = __ldg((const unsigned int*)(hh + rb));
            bh[ns][1] = __ldg((const unsigned int*)(hh + rb + 8));
            bl[ns][0] = __ldg((const unsigned int*)(hl + rb));
            bl[ns][1] = __ldg((const unsigned int*)(hl + rb + 8));
        }
#pragma unroll
        for (int cs = 0; cs < 2; cs++)
#pragma unroll
            for (int ns = 0; ns < 4; ns++) {
                mma_bf16(d[cs][ns], ah[cs], bh[ns]);   // hi*hi
                mma_bf16(d[cs][ns], al[cs], bh[ns]);   // lo*hi
                mma_bf16(d[cs][ns], ah[cs], bl[ns]);   // hi*lo
            }
    }

    // epilogue: bn2 + residual + relu
#pragma unroll
    for (int cs = 0; cs < 2; cs++) {
        int c0r = cbase + cs * 16 + g;
        int c1r = c0r + 8;
        float sc0 = scs[c0r], sh0 = shs[c0r];
        float sc1 = scs[c1r], sh1 = shs[c1r];
#pragma unroll
        for (int ns = 0; ns < 4; ns++) {
            int n = nbase + ns * 8 + 2 * tg;
            const float* dd = d[cs][ns];
            float2 f0 = *(const float2*)&g_f[b * 16384 + c0r * 256 + n];
            float2 f1 = *(const float2*)&g_f[b * 16384 + c1r * 256 + n];
            float2 r0, r1;
            r0.x = fmaxf(fmaf(dd[0], sc0, sh0) + f0.x, 0.f);
            r0.y = fmaxf(fmaf(dd[1], sc0, sh0) + f0.y, 0.f);
            r1.x = fmaxf(fmaf(dd[2], sc1, sh1) + f1.x, 0.f);
            r1.y = fmaxf(fmaf(dd[3], sc1, sh1) + f1.y, 0.f);
            *(float2*)&out[b * 16384 + c0r * 256 + n] = r0;
            *(float2*)&out[b * 16384 + c1r * 256 + n] = r1;
        }
    }
}

// ---------------- launch ----------------
extern "C" void kernel_launch(void* const* d_in, const int* in_sizes, int n_in,
                              void* d_out, int out_size) {
    int base = (in_sizes[2] == 512) ? 2 : 3;

    const float* x          = (const float*)d_in[0];
    const int*   stroke     = (const int*)d_in[1];
    const float* ga_q_w     = (const float*)d_in[base + 0];
    const float* ga_k_w     = (const float*)d_in[base + 1];
    const float* ga_v_w     = (const float*)d_in[base + 2];
    const float* ga_v_b     = (const float*)d_in[base + 3];
    const float* ga_bn_p    = (const float*)d_in[base + 4];
    const float* ga_lb_w    = (const float*)d_in[base + 5];
    const float* ga_lb_bn_p = (const float*)d_in[base + 6];
    const float* sa_q_w     = (const float*)d_in[base + 7];
    const float* sa_k_w     = (const float*)d_in[base + 8];
    const float* sa_v_w     = (const float*)d_in[base + 9];
    const float* sa_v_b     = (const float*)d_in[base + 10];
    const float* sa_bn_p    = (const float*)d_in[base + 11];
    const float* sa_lb_w    = (const float*)d_in[base + 12];
    const float* sa_lb_bn_p = (const float*)d_in[base + 13];
    const float* mlp_w1     = (const float*)d_in[base + 14];
    const float* mlp_bn1_p  = (const float*)d_in[base + 15];
    const float* mlp_w2     = (const float*)d_in[base + 16];
    const float* mlp_bn2_p  = (const float*)d_in[base + 17];

    cudaFuncSetAttribute(attn_kernel, cudaFuncAttributeMaxDynamicSharedMemorySize, ATTN_SMEM_BYTES);
    cudaFuncSetAttribute(mlp1_kernel, cudaFuncAttributeMaxDynamicSharedMemorySize, M1_SMEM_BYTES);

    proj_kernel<<<dim3(64, 16), 128>>>(x, ga_q_w, ga_k_w, ga_v_w, ga_lb_w,
                                       sa_q_w, sa_k_w, sa_v_w, sa_lb_w);
    w2split_kernel<<<8, 256>>>(mlp_w2);
    attn_kernel<<<dim3(64, 4), 256, ATTN_SMEM_BYTES>>>(stroke, ga_v_b, sa_v_b,
                                                       ga_bn_p, ga_lb_bn_p,
                                                       sa_bn_p, sa_lb_bn_p);
    mlp1_kernel<<<dim3(8, 64), 256, M1_SMEM_BYTES>>>(mlp_w1, mlp_bn1_p);
    mlp2_mma_kernel<<<dim3(4, 64), 128>>>(mlp_bn2_p, (float*)d_out);
}